// round 1
// baseline (speedup 1.0000x reference)
#include <cuda_runtime.h>

// Problem: out[b,co,h,w] = conv3x3_zeropad(x, W)[b,co,h,w] + bias[co]
//                          - THETA * stencil(channel_sum(x))[b,h,w]
// B=32, Cin=Cout=128, H=W=128, fp32, NCHW / OIHW.
#define THETA 0.7f

#define NB   32
#define NC   128
#define NH   128
#define NW   128
#define HWSZ (NH * NW)          // 16384
#define IMG  (NC * HWSZ)        // 2097152 floats per batch image

// Scratch (allocation-free per harness rules): channel sums and theta*diff.
static __device__ float g_s[NB * HWSZ];
static __device__ float g_d[NB * HWSZ];

// ---------------------------------------------------------------------------
// Kernel 1: s[b,h,w] = sum_c x[b,c,h,w]
// ---------------------------------------------------------------------------
__global__ void k_chansum(const float* __restrict__ x) {
    int idx = blockIdx.x * blockDim.x + threadIdx.x;   // b*16384 + hw
    int b  = idx >> 14;
    int hw = idx & (HWSZ - 1);
    const float* p = x + (size_t)b * IMG + hw;
    float s = 0.f;
#pragma unroll 16
    for (int c = 0; c < NC; ++c) s += p[(size_t)c << 14];
    g_s[idx] = s;
}

// ---------------------------------------------------------------------------
// Kernel 2: g_d = THETA * (s_up + s_dn + s_lf + s_rt - 4*s), edge-replicated
// ---------------------------------------------------------------------------
__global__ void k_stencil() {
    int idx = blockIdx.x * blockDim.x + threadIdx.x;
    int b  = idx >> 14;
    int hw = idx & (HWSZ - 1);
    int h = hw >> 7, w = hw & 127;
    const float* s = g_s + (b << 14);
    float c  = s[hw];
    float up = s[((h > 0   ? h - 1 : 0  ) << 7) + w];
    float dn = s[((h < 127 ? h + 1 : 127) << 7) + w];
    float lf = s[(h << 7) + (w > 0   ? w - 1 : 0  )];
    float rt = s[(h << 7) + (w < 127 ? w + 1 : 127)];
    g_d[idx] = THETA * (up + dn + lf + rt - 4.f * c);
}

// ---------------------------------------------------------------------------
// Kernel 3: direct conv, register-blocked.
// Block: 64 cout x (2 rows x 128 w) outputs, 256 threads.
// Thread: 8 cout x 8 positions register tile.
//   tid = wthr (0..31) + 32*cthr (0..7)
//   position j: w = wthr + 32*(j&3), h = h0 + (j>>2)
//   cout      : co = cog*64 + cthr*8 + i
// Cin processed in chunks of 4 through shared memory.
// ---------------------------------------------------------------------------
__global__ __launch_bounds__(256, 2)
void k_conv(const float* __restrict__ x, const float* __restrict__ Wt,
            const float* __restrict__ bias, float* __restrict__ out) {
    __shared__ __align__(16) float xs[4][4][132];  // [ci][row(h0-1..h0+2)][col(w=-1..128)+1]
    __shared__ __align__(16) float ws[4][9][64];   // [ci][k][cout]

    const int tid  = threadIdx.x;
    const int wthr = tid & 31;
    const int cthr = tid >> 5;
    const int h0   = blockIdx.x * 2;     // 64 h-tiles
    const int cog  = blockIdx.y;         // 2 cout groups of 64
    const int b    = blockIdx.z;

    const float* xb = x + (size_t)b * IMG;

    float acc[8][8];
#pragma unroll
    for (int i = 0; i < 8; ++i)
#pragma unroll
        for (int j = 0; j < 8; ++j) acc[i][j] = 0.f;

    for (int cc = 0; cc < NC / 4; ++cc) {
        const int ci0 = cc * 4;
        __syncthreads();   // previous chunk's compute must finish before overwrite

        // ---- load x tile: 4 ci x 4 rows x 130 cols = 2080 elems ----
        for (int e = tid; e < 4 * 4 * 130; e += 256) {
            int ci  = e / 520;            // 4*130
            int rem = e - ci * 520;
            int r   = rem / 130;
            int col = rem - r * 130;
            int gh  = h0 - 1 + r;
            int gw  = col - 1;
            float v = 0.f;
            if ((unsigned)gh < (unsigned)NH && (unsigned)gw < (unsigned)NW)
                v = xb[((ci0 + ci) << 14) + (gh << 7) + gw];
            xs[ci][r][col] = v;
        }
        // ---- load W tile: 4 ci x 9 k x 64 co = 2304 elems ----
        for (int e = tid; e < 4 * 9 * 64; e += 256) {
            int ci  = e / 576;
            int rem = e - ci * 576;
            int k   = rem >> 6;
            int co  = rem & 63;
            ws[ci][k][co] = Wt[((size_t)(cog * 64 + co) * NC + (ci0 + ci)) * 9 + k];
        }
        __syncthreads();

        // ---- compute ----
#pragma unroll
        for (int ci = 0; ci < 4; ++ci) {
#pragma unroll
            for (int kh = 0; kh < 3; ++kh) {
#pragma unroll
                for (int kw = 0; kw < 3; ++kw) {
                    const float* wp = &ws[ci][kh * 3 + kw][cthr * 8];
                    float4 wa = *(const float4*)(wp);
                    float4 wb2 = *(const float4*)(wp + 4);
                    float wv[8] = {wa.x, wa.y, wa.z, wa.w, wb2.x, wb2.y, wb2.z, wb2.w};
                    float xv[8];
#pragma unroll
                    for (int j = 0; j < 8; ++j)
                        xv[j] = xs[ci][(j >> 2) + kh][wthr + ((j & 3) << 5) + kw];
#pragma unroll
                    for (int i = 0; i < 8; ++i)
#pragma unroll
                        for (int j = 0; j < 8; ++j)
                            acc[i][j] = fmaf(wv[i], xv[j], acc[i][j]);
                }
            }
        }
    }

    // ---- epilogue: + bias - theta*diff ----
    float bv[8];
#pragma unroll
    for (int i = 0; i < 8; ++i) bv[i] = __ldg(&bias[cog * 64 + cthr * 8 + i]);

#pragma unroll
    for (int j = 0; j < 8; ++j) {
        int w = wthr + ((j & 3) << 5);
        int h = h0 + (j >> 2);
        float dv = g_d[(b << 14) + (h << 7) + w];
#pragma unroll
        for (int i = 0; i < 8; ++i) {
            int co = cog * 64 + cthr * 8 + i;
            out[(size_t)b * IMG + ((size_t)co << 14) + (h << 7) + w] =
                acc[i][j] + bv[i] - dv;
        }
    }
}

// ---------------------------------------------------------------------------
extern "C" void kernel_launch(void* const* d_in, const int* in_sizes, int n_in,
                              void* d_out, int out_size) {
    const float* x  = (const float*)d_in[0];   // [32,128,128,128]
    const float* Wt = (const float*)d_in[1];   // [128,128,3,3]
    const float* bb = (const float*)d_in[2];   // [128]
    float* out = (float*)d_out;

    (void)in_sizes; (void)n_in; (void)out_size;

    k_chansum<<<NB * HWSZ / 256, 256>>>(x);
    k_stencil<<<NB * HWSZ / 256, 256>>>();
    dim3 grid(NH / 2, 2, NB);
    k_conv<<<grid, 256>>>(x, Wt, bb, out);
}

// round 2
// speedup vs baseline: 1.0013x; 1.0013x over previous
#include <cuda_runtime.h>

// Problem: out[b,co,h,w] = conv3x3_zeropad(x, W)[b,co,h,w] + bias[co]
//                          - THETA * stencil(channel_sum(x))[b,h,w]
// B=32, Cin=Cout=128, H=W=128, fp32, NCHW / OIHW.
#define THETA 0.7f

#define NB   32
#define NC   128
#define NH   128
#define NW   128
#define HWSZ (NH * NW)          // 16384
#define IMG  (NC * HWSZ)        // 2097152 floats per batch image

// Scratch (allocation-free per harness rules): channel sums and theta*diff.
static __device__ float g_s[NB * HWSZ];
static __device__ float g_d[NB * HWSZ];

// ---------------------------------------------------------------------------
// Kernel 1: s[b,h,w] = sum_c x[b,c,h,w]
// ---------------------------------------------------------------------------
__global__ void k_chansum(const float* __restrict__ x) {
    int idx = blockIdx.x * blockDim.x + threadIdx.x;   // b*16384 + hw
    int b  = idx >> 14;
    int hw = idx & (HWSZ - 1);
    const float* p = x + (size_t)b * IMG + hw;
    float s = 0.f;
#pragma unroll 16
    for (int c = 0; c < NC; ++c) s += p[(size_t)c << 14];
    g_s[idx] = s;
}

// ---------------------------------------------------------------------------
// Kernel 2: g_d = THETA * (s_up + s_dn + s_lf + s_rt - 4*s), edge-replicated
// ---------------------------------------------------------------------------
__global__ void k_stencil() {
    int idx = blockIdx.x * blockDim.x + threadIdx.x;
    int b  = idx >> 14;
    int hw = idx & (HWSZ - 1);
    int h = hw >> 7, w = hw & 127;
    const float* s = g_s + (b << 14);
    float c  = s[hw];
    float up = s[((h > 0   ? h - 1 : 0  ) << 7) + w];
    float dn = s[((h < 127 ? h + 1 : 127) << 7) + w];
    float lf = s[(h << 7) + (w > 0   ? w - 1 : 0  )];
    float rt = s[(h << 7) + (w < 127 ? w + 1 : 127)];
    g_d[idx] = THETA * (up + dn + lf + rt - 4.f * c);
}

// ---------------------------------------------------------------------------
// Kernel 3: direct conv, register-blocked.
// Block: 64 cout x (2 rows x 128 w) outputs, 256 threads.
// Thread: 8 cout x 8 positions register tile.
//   tid = wthr (0..31) + 32*cthr (0..7)
//   position j: w = wthr + 32*(j&3), h = h0 + (j>>2)
//   cout      : co = cog*64 + cthr*8 + i
// Cin processed in chunks of 4 through shared memory.
// ---------------------------------------------------------------------------
__global__ __launch_bounds__(256, 2)
void k_conv(const float* __restrict__ x, const float* __restrict__ Wt,
            const float* __restrict__ bias, float* __restrict__ out) {
    __shared__ __align__(16) float xs[4][4][132];  // [ci][row(h0-1..h0+2)][col(w=-1..128)+1]
    __shared__ __align__(16) float ws[4][9][64];   // [ci][k][cout]

    const int tid  = threadIdx.x;
    const int wthr = tid & 31;
    const int cthr = tid >> 5;
    const int h0   = blockIdx.x * 2;     // 64 h-tiles
    const int cog  = blockIdx.y;         // 2 cout groups of 64
    const int b    = blockIdx.z;

    const float* xb = x + (size_t)b * IMG;

    float acc[8][8];
#pragma unroll
    for (int i = 0; i < 8; ++i)
#pragma unroll
        for (int j = 0; j < 8; ++j) acc[i][j] = 0.f;

    for (int cc = 0; cc < NC / 4; ++cc) {
        const int ci0 = cc * 4;
        __syncthreads();   // previous chunk's compute must finish before overwrite

        // ---- load x tile: 4 ci x 4 rows x 130 cols = 2080 elems ----
        for (int e = tid; e < 4 * 4 * 130; e += 256) {
            int ci  = e / 520;            // 4*130
            int rem = e - ci * 520;
            int r   = rem / 130;
            int col = rem - r * 130;
            int gh  = h0 - 1 + r;
            int gw  = col - 1;
            float v = 0.f;
            if ((unsigned)gh < (unsigned)NH && (unsigned)gw < (unsigned)NW)
                v = xb[((ci0 + ci) << 14) + (gh << 7) + gw];
            xs[ci][r][col] = v;
        }
        // ---- load W tile: 4 ci x 9 k x 64 co = 2304 elems ----
        for (int e = tid; e < 4 * 9 * 64; e += 256) {
            int ci  = e / 576;
            int rem = e - ci * 576;
            int k   = rem >> 6;
            int co  = rem & 63;
            ws[ci][k][co] = Wt[((size_t)(cog * 64 + co) * NC + (ci0 + ci)) * 9 + k];
        }
        __syncthreads();

        // ---- compute ----
#pragma unroll
        for (int ci = 0; ci < 4; ++ci) {
#pragma unroll
            for (int kh = 0; kh < 3; ++kh) {
#pragma unroll
                for (int kw = 0; kw < 3; ++kw) {
                    const float* wp = &ws[ci][kh * 3 + kw][cthr * 8];
                    float4 wa = *(const float4*)(wp);
                    float4 wb2 = *(const float4*)(wp + 4);
                    float wv[8] = {wa.x, wa.y, wa.z, wa.w, wb2.x, wb2.y, wb2.z, wb2.w};
                    float xv[8];
#pragma unroll
                    for (int j = 0; j < 8; ++j)
                        xv[j] = xs[ci][(j >> 2) + kh][wthr + ((j & 3) << 5) + kw];
#pragma unroll
                    for (int i = 0; i < 8; ++i)
#pragma unroll
                        for (int j = 0; j < 8; ++j)
                            acc[i][j] = fmaf(wv[i], xv[j], acc[i][j]);
                }
            }
        }
    }

    // ---- epilogue: + bias - theta*diff ----
    float bv[8];
#pragma unroll
    for (int i = 0; i < 8; ++i) bv[i] = __ldg(&bias[cog * 64 + cthr * 8 + i]);

#pragma unroll
    for (int j = 0; j < 8; ++j) {
        int w = wthr + ((j & 3) << 5);
        int h = h0 + (j >> 2);
        float dv = g_d[(b << 14) + (h << 7) + w];
#pragma unroll
        for (int i = 0; i < 8; ++i) {
            int co = cog * 64 + cthr * 8 + i;
            out[(size_t)b * IMG + ((size_t)co << 14) + (h << 7) + w] =
                acc[i][j] + bv[i] - dv;
        }
    }
}

// ---------------------------------------------------------------------------
extern "C" void kernel_launch(void* const* d_in, const int* in_sizes, int n_in,
                              void* d_out, int out_size) {
    const float* x  = (const float*)d_in[0];   // [32,128,128,128]
    const float* Wt = (const float*)d_in[1];   // [128,128,3,3]
    const float* bb = (const float*)d_in[2];   // [128]
    float* out = (float*)d_out;

    (void)in_sizes; (void)n_in; (void)out_size;

    k_chansum<<<NB * HWSZ / 256, 256>>>(x);
    k_stencil<<<NB * HWSZ / 256, 256>>>();
    dim3 grid(NH / 2, 2, NB);
    k_conv<<<grid, 256>>>(x, Wt, bb, out);
}

// round 5
// speedup vs baseline: 2.7725x; 2.7689x over previous
#include <cuda_runtime.h>
#include <cuda_bf16.h>
#include <cstdint>

#define THETA 0.7f
#define NB   32
#define NC   128
#define NH   128
#define NW   128
#define HWSZ (NH * NW)
#define IMG  (NC * HWSZ)

// ---------------- scratch (static device memory; no allocation) -------------
// xTp: [b][hp=h+1 (0..129)][cc(2)][sx(hi,lo)] 16KB blocks, each [128 w][64 ci]
// bf16, SW128 swizzle baked into the byte layout.
static __device__ __align__(1024) unsigned char g_xTp[(size_t)32 * 130 * 2 * 2 * 16384];
// Wp: [cc(2)][kw(3)][kh(3)][sw(hi,lo)] 16KB blocks, each [128 co][64 ci] SW128-baked.
static __device__ __align__(1024) unsigned char g_Wp[36 * 16384];
static __device__ float g_sp[2][NB * HWSZ];   // partial channel sums (per cc half)
static __device__ float g_d[NB * HWSZ];       // THETA * stencil

// ---------------- PTX helpers ----------------------------------------------
__device__ __forceinline__ uint32_t smem_u32(const void* p) {
    uint32_t a;
    asm("{ .reg .u64 t; cvta.to.shared.u64 t, %1; cvt.u32.u64 %0, t; }" : "=r"(a) : "l"(p));
    return a;
}
#define MBAR_INIT(a, n) asm volatile("mbarrier.init.shared.b64 [%0], %1;" :: "r"(a), "r"(n) : "memory")
#define MBAR_EXPECT_TX(a, b) asm volatile("mbarrier.arrive.expect_tx.shared.b64 _, [%0], %1;" :: "r"(a), "r"(b) : "memory")
__device__ __forceinline__ void mbar_wait(uint32_t mbar, uint32_t parity) {
    asm volatile(
        "{\n\t.reg .pred P;\n\t"
        "W_%=:\n\t"
        "mbarrier.try_wait.parity.acquire.cta.shared::cta.b64 P, [%0], %1, 0x989680;\n\t"
        "@!P bra W_%=;\n\t}" :: "r"(mbar), "r"(parity) : "memory");
}
__device__ __forceinline__ void bulk_g2s(uint32_t dst, const void* src, uint32_t bytes, uint32_t mbar) {
    asm volatile(
        "cp.async.bulk.shared::cta.global.mbarrier::complete_tx::bytes [%0], [%1], %2, [%3];"
        :: "r"(dst), "l"(src), "r"(bytes), "r"(mbar) : "memory");
}
__device__ __forceinline__ void ldsm4(uint32_t* r, uint32_t addr) {
    asm volatile("ldmatrix.sync.aligned.m8n8.x4.shared.b16 {%0,%1,%2,%3}, [%4];"
                 : "=r"(r[0]), "=r"(r[1]), "=r"(r[2]), "=r"(r[3]) : "r"(addr));
}
__device__ __forceinline__ void mma16816(float* c, const uint32_t* a, const uint32_t* b) {
    asm volatile(
        "mma.sync.aligned.m16n8k16.row.col.f32.bf16.bf16.f32 "
        "{%0,%1,%2,%3}, {%4,%5,%6,%7}, {%8,%9}, {%0,%1,%2,%3};"
        : "+f"(c[0]), "+f"(c[1]), "+f"(c[2]), "+f"(c[3])
        : "r"(a[0]), "r"(a[1]), "r"(a[2]), "r"(a[3]), "r"(b[0]), "r"(b[1]));
}
__device__ __forceinline__ uint32_t swz(uint32_t x) { return x ^ ((x >> 3) & 0x70); }

// ---------------- pre-pass kernels ------------------------------------------
__global__ void k_stencil() {
    int idx = blockIdx.x * blockDim.x + threadIdx.x;
    int b = idx >> 14, hw = idx & (HWSZ - 1);
    int h = hw >> 7, w = hw & 127;
    int base = b << 14;
    int hu = (h > 0   ? h - 1 : 0  ), hd = (h < 127 ? h + 1 : 127);
    int wl = (w > 0   ? w - 1 : 0  ), wr = (w < 127 ? w + 1 : 127);
    float c  = g_sp[0][base + hw]            + g_sp[1][base + hw];
    float up = g_sp[0][base + (hu << 7) + w] + g_sp[1][base + (hu << 7) + w];
    float dn = g_sp[0][base + (hd << 7) + w] + g_sp[1][base + (hd << 7) + w];
    float lf = g_sp[0][base + (h << 7) + wl] + g_sp[1][base + (h << 7) + wl];
    float rt = g_sp[0][base + (h << 7) + wr] + g_sp[1][base + (h << 7) + wr];
    g_d[idx] = THETA * (up + dn + lf + rt - 4.f * c);
}

// zero the pad rows hp=0 and hp=129
__global__ void k_zero() {
    int i = blockIdx.x * blockDim.x + threadIdx.x;   // 262144 float4s total
    int b = i >> 13, rem = i & 8191;
    int pr = rem >> 12, j = rem & 4095;
    size_t off = ((size_t)(b * 130 + (pr ? 129 : 0))) * 65536 + (size_t)j * 16;
    *(float4*)(g_xTp + off) = make_float4(0.f, 0.f, 0.f, 0.f);
}

// weights: split hi/lo + SW128-bake; layout [cc][kw][kh][sw]
__global__ void k_prep_w(const float* __restrict__ W) {
    int cc = blockIdx.x, kh = blockIdx.y, kw = blockIdx.z;
    size_t base = (size_t)((cc * 3 + kw) * 3 + kh) * 32768;
    for (int i = threadIdx.x; i < 8192; i += 256) {
        int co = i >> 6, ci = i & 63;
        float v = W[((size_t)co * 128 + cc * 64 + ci) * 9 + kh * 3 + kw];
        __nv_bfloat16 h = __float2bfloat16(v);
        __nv_bfloat16 l = __float2bfloat16(v - __bfloat162float(h));
        uint32_t byte = (uint32_t)co * 128 + ci * 2;
        uint32_t sw = swz(byte);
        *(unsigned short*)(g_Wp + base + sw)         = __bfloat16_as_ushort(h);
        *(unsigned short*)(g_Wp + base + 16384 + sw) = __bfloat16_as_ushort(l);
    }
}

// x: transpose [ci][w] -> [w][ci], bf16 split, bake swizzle, + partial chansum
__global__ void k_prep_x(const float* __restrict__ x) {
    extern __shared__ char ps[];
    float* xin = (float*)ps;                                  // [64][129]
    unsigned short* oh = (unsigned short*)(ps + 33024);       // 16KB
    unsigned short* ol = (unsigned short*)(ps + 49408);       // 16KB
    int cc = blockIdx.x, h = blockIdx.y, b = blockIdx.z;
    const float* src = x + (size_t)b * IMG + ((size_t)cc * 64) * 16384 + (size_t)h * 128;
    for (int i = threadIdx.x; i < 8192; i += 256) {
        int ci = i >> 7, w = i & 127;
        xin[ci * 129 + w] = src[(size_t)ci * 16384 + w];
    }
    __syncthreads();
    if (threadIdx.x < 128) {
        int w = threadIdx.x;
        float s = 0.f;
#pragma unroll 16
        for (int ci = 0; ci < 64; ++ci) s += xin[ci * 129 + w];
        g_sp[cc][((size_t)b << 14) + ((size_t)h << 7) + w] = s;
    }
    for (int i = threadIdx.x; i < 8192; i += 256) {
        int w = i >> 6, ci = i & 63;
        float v = xin[ci * 129 + w];
        __nv_bfloat16 hh = __float2bfloat16(v);
        __nv_bfloat16 ll = __float2bfloat16(v - __bfloat162float(hh));
        uint32_t sw = swz((uint32_t)w * 128 + ci * 2);
        oh[sw >> 1] = __bfloat16_as_ushort(hh);
        ol[sw >> 1] = __bfloat16_as_ushort(ll);
    }
    __syncthreads();
    unsigned char* dst = g_xTp + ((size_t)((b * 130 + h + 1) * 2 + cc) * 2) * 16384;
    float4* d0 = (float4*)dst;
    const float4* s0 = (const float4*)oh;
    const float4* s1 = (const float4*)ol;
    for (int i = threadIdx.x; i < 1024; i += 256) { d0[i] = s0[i]; d0[1024 + i] = s1[i]; }
}

// ---------------- main mma.sync kernel ---------------------------------------
// SMEM: [0..64) mbarriers (xbar @8, wbar0 @16, wbar1 @24)
//       X: 1024 + 6*16384 = 98304   ([kh][sx] blocks)
//       W: 99328 + 2*32768          (double-buffered hi+lo chunk)
//       out_s: 164864 + 128*131*4 = 67072  -> total 231936
#define X_OFF 1024u
#define W_OFF 99328u
#define O_OFF 164864u
#define SMEM_TOTAL 231936

__global__ void __launch_bounds__(256, 1) k_main(const float* __restrict__ bias,
                                                 float* __restrict__ out) {
    extern __shared__ __align__(1024) char smem[];
    uint32_t sb = smem_u32(smem);
    const int tid = threadIdx.x, wid = tid >> 5, lane = tid & 31;
    const int h = blockIdx.x, b = blockIdx.y;
    const unsigned char* xp = g_xTp + (size_t)b * 130 * 65536;

    if (tid == 0) { MBAR_INIT(sb + 8, 1); MBAR_INIT(sb + 16, 1); MBAR_INIT(sb + 24, 1); }

    float* outs = (float*)(smem + O_OFF);    // [128 co][131]
    for (int i = tid; i < 128 * 131; i += 256) outs[i] = 0.f;
    __syncthreads();

    // prologue: X for cc=0, W chunks 0 and 1
    if (tid == 0) {
        MBAR_EXPECT_TX(sb + 8, 98304u);
#pragma unroll
        for (int kh = 0; kh < 3; ++kh)
#pragma unroll
            for (int sx = 0; sx < 2; ++sx)
                bulk_g2s(sb + X_OFF + (uint32_t)(kh * 2 + sx) * 16384u,
                         xp + (size_t)((h + kh) * 4 + sx) * 16384, 16384u, sb + 8);
        MBAR_EXPECT_TX(sb + 16, 32768u);
        bulk_g2s(sb + W_OFF, g_Wp, 32768u, sb + 16);
        MBAR_EXPECT_TX(sb + 24, 32768u);
        bulk_g2s(sb + W_OFF + 32768u, g_Wp + 32768, 32768u, sb + 24);
    }

    // per-thread ldmatrix source coordinates
    const int a_row = wid * 16 + ((lane & 7) | (((lane >> 3) & 1) << 3));
    const uint32_t a_kb = (uint32_t)((lane >> 4) << 4);
    const int b_n  = (lane & 7) + ((lane >> 4) << 3);
    const uint32_t b_kb = (uint32_t)(((lane >> 3) & 1) << 4);

    float C[16][4];

    for (int q = 0; q < 18; ++q) {
        const int cc = q / 9, r9 = q % 9, kw = r9 / 3, kh = r9 % 3;

        if (q == 9 && tid == 0) {   // reload X for cc=1 (cc=0 fully consumed)
            MBAR_EXPECT_TX(sb + 8, 98304u);
#pragma unroll
            for (int k2 = 0; k2 < 3; ++k2)
#pragma unroll
                for (int sx = 0; sx < 2; ++sx)
                    bulk_g2s(sb + X_OFF + (uint32_t)(k2 * 2 + sx) * 16384u,
                             xp + (size_t)((h + k2) * 4 + 2 + sx) * 16384, 16384u, sb + 8);
        }
        if (q == 0) mbar_wait(sb + 8, 0);
        if (q == 9) mbar_wait(sb + 8, 1);
        mbar_wait(sb + 16u + (uint32_t)((q & 1) << 3), (uint32_t)(q >> 1) & 1u);

        if (kh == 0) {
#pragma unroll
            for (int nt = 0; nt < 16; ++nt)
#pragma unroll
                for (int i = 0; i < 4; ++i) C[nt][i] = 0.f;
        }

        const uint32_t wb  = sb + W_OFF + (uint32_t)((q & 1) << 15);
        const uint32_t xhb = sb + X_OFF + (uint32_t)(kh * 2) * 16384u;

#pragma unroll
        for (int ks = 0; ks < 4; ++ks) {
            uint32_t ah[4], al[4], bh[32], bl[32];
            uint32_t aoff = swz((uint32_t)a_row * 128u + (uint32_t)ks * 32u + a_kb);
            ldsm4(ah, wb + aoff);
            ldsm4(al, wb + 16384u + aoff);
#pragma unroll
            for (int ntp = 0; ntp < 8; ++ntp) {
                uint32_t boff = swz((uint32_t)(b_n + ntp * 16) * 128u + (uint32_t)ks * 32u + b_kb);
                ldsm4(&bh[ntp * 4], xhb + boff);
                ldsm4(&bl[ntp * 4], xhb + 16384u + boff);
            }
            // term 0: Whi * xhi
#pragma unroll
            for (int nt = 0; nt < 16; ++nt)
                mma16816(C[nt], ah, &bh[((nt >> 1) << 2) + ((nt & 1) << 1)]);
            // term 1: Whi * xlo
#pragma unroll
            for (int nt = 0; nt < 16; ++nt)
                mma16816(C[nt], ah, &bl[((nt >> 1) << 2) + ((nt & 1) << 1)]);
            // term 2: Wlo * xhi
#pragma unroll
            for (int nt = 0; nt < 16; ++nt)
                mma16816(C[nt], al, &bh[((nt >> 1) << 2) + ((nt & 1) << 1)]);
        }

        if (kh == 2) {
            // accumulate C_kw into out_s with w-shift: out_s[co][n - kw + 2] += C[co][n]
            const int row0 = wid * 16 + (lane >> 2);
            const int cshift = 2 - kw + 2 * (lane & 3);
#pragma unroll
            for (int nt = 0; nt < 16; ++nt) {
                int colb = nt * 8 + cshift;
                float* p0 = &outs[row0 * 131 + colb];
                float* p1 = &outs[(row0 + 8) * 131 + colb];
                p0[0] += C[nt][0];
                p0[1] += C[nt][1];
                p1[0] += C[nt][2];
                p1[1] += C[nt][3];
            }
        }

        __syncthreads();   // buffer q fully consumed (ldsm + epilogue) before refill
        if (tid == 0 && q + 2 < 18) {
            uint32_t mb = sb + 16u + (uint32_t)((q & 1) << 3);
            MBAR_EXPECT_TX(mb, 32768u);
            bulk_g2s(sb + W_OFF + (uint32_t)((q & 1) << 15),
                     g_Wp + (size_t)(q + 2) * 32768, 32768u, mb);
        }
    }

    // final: out = out_s[co][w+1] + bias[co] - g_d
    const float* gd = g_d + ((size_t)b << 14) + ((size_t)h << 7);
    for (int i = tid; i < 16384; i += 256) {
        int co = i >> 7, w = i & 127;
        float v = outs[co * 131 + w + 1] + __ldg(&bias[co]) - __ldg(&gd[w]);
        out[(size_t)b * IMG + ((size_t)co << 14) + (h << 7) + w] = v;
    }
}

// ---------------------------------------------------------------------------
extern "C" void kernel_launch(void* const* d_in, const int* in_sizes, int n_in,
                              void* d_out, int out_size) {
    const float* x  = (const float*)d_in[0];
    const float* Wt = (const float*)d_in[1];
    const float* bb = (const float*)d_in[2];
    float* out = (float*)d_out;
    (void)in_sizes; (void)n_in; (void)out_size;

    cudaFuncSetAttribute(k_prep_x, cudaFuncAttributeMaxDynamicSharedMemorySize, 65792);
    cudaFuncSetAttribute(k_main,   cudaFuncAttributeMaxDynamicSharedMemorySize, SMEM_TOTAL);

    k_prep_w<<<dim3(2, 3, 3), 256>>>(Wt);
    k_zero<<<1024, 256>>>();
    k_prep_x<<<dim3(2, 128, 32), 256, 65792>>>(x);
    k_stencil<<<NB * HWSZ / 256, 256>>>();
    k_main<<<dim3(128, 32), 256, SMEM_TOTAL>>>(bb, out);
}

// round 6
// speedup vs baseline: 3.9155x; 1.4123x over previous
#include <cuda_runtime.h>
#include <cuda_fp16.h>
#include <cstdint>

#define THETA 0.7f
#define NB   32
#define NC   128
#define NH   128
#define NW   128
#define HWSZ (NH * NW)
#define IMG  (NC * HWSZ)

// ---------------- scratch (static device memory; no allocation) -------------
// xTp: [b][hp=h+1 (0..129)][cc(2)][sx(hi,lo)] 16KB blocks, each [128 w][64 ci]
// fp16, SW128 swizzle baked into the byte layout.
static __device__ __align__(1024) unsigned char g_xTp[(size_t)32 * 130 * 2 * 2 * 16384];
// Wp: 18 blocks [cc(2)][kw(3)][kh(3)], each 16KB [128 co][64 ci] fp16 (hi only).
static __device__ __align__(1024) unsigned char g_Wp[18 * 16384];
static __device__ float g_sp[2][NB * HWSZ];   // partial channel sums
static __device__ float g_d[NB * HWSZ];       // THETA * stencil

// ---------------- PTX helpers ----------------------------------------------
__device__ __forceinline__ uint32_t smem_u32(const void* p) {
    uint32_t a;
    asm("{ .reg .u64 t; cvta.to.shared.u64 t, %1; cvt.u32.u64 %0, t; }" : "=r"(a) : "l"(p));
    return a;
}
#define MBAR_INIT(a, n) asm volatile("mbarrier.init.shared.b64 [%0], %1;" :: "r"(a), "r"(n) : "memory")
#define MBAR_EXPECT_TX(a, b) asm volatile("mbarrier.arrive.expect_tx.shared.b64 _, [%0], %1;" :: "r"(a), "r"(b) : "memory")
__device__ __forceinline__ void mbar_wait(uint32_t mbar, uint32_t parity) {
    asm volatile(
        "{\n\t.reg .pred P;\n\t"
        "W_%=:\n\t"
        "mbarrier.try_wait.parity.acquire.cta.shared::cta.b64 P, [%0], %1, 0x989680;\n\t"
        "@!P bra W_%=;\n\t}" :: "r"(mbar), "r"(parity) : "memory");
}
__device__ __forceinline__ void bulk_g2s(uint32_t dst, const void* src, uint32_t bytes, uint32_t mbar) {
    asm volatile(
        "cp.async.bulk.shared::cta.global.mbarrier::complete_tx::bytes [%0], [%1], %2, [%3];"
        :: "r"(dst), "l"(src), "r"(bytes), "r"(mbar) : "memory");
}
__device__ __forceinline__ void ldsm4(uint32_t* r, uint32_t addr) {
    asm volatile("ldmatrix.sync.aligned.m8n8.x4.shared.b16 {%0,%1,%2,%3}, [%4];"
                 : "=r"(r[0]), "=r"(r[1]), "=r"(r[2]), "=r"(r[3]) : "r"(addr));
}
__device__ __forceinline__ void mma16816(float* c, const uint32_t* a, const uint32_t* b) {
    asm volatile(
        "mma.sync.aligned.m16n8k16.row.col.f32.f16.f16.f32 "
        "{%0,%1,%2,%3}, {%4,%5,%6,%7}, {%8,%9}, {%0,%1,%2,%3};"
        : "+f"(c[0]), "+f"(c[1]), "+f"(c[2]), "+f"(c[3])
        : "r"(a[0]), "r"(a[1]), "r"(a[2]), "r"(a[3]), "r"(b[0]), "r"(b[1]));
}
__device__ __forceinline__ uint32_t swz(uint32_t x) { return x ^ ((x >> 3) & 0x70); }

// ---------------- pre-pass kernels ------------------------------------------
__global__ void k_stencil() {
    int idx = blockIdx.x * blockDim.x + threadIdx.x;
    int b = idx >> 14, hw = idx & (HWSZ - 1);
    int h = hw >> 7, w = hw & 127;
    int base = b << 14;
    int hu = (h > 0   ? h - 1 : 0  ), hd = (h < 127 ? h + 1 : 127);
    int wl = (w > 0   ? w - 1 : 0  ), wr = (w < 127 ? w + 1 : 127);
    float c  = g_sp[0][base + hw]            + g_sp[1][base + hw];
    float up = g_sp[0][base + (hu << 7) + w] + g_sp[1][base + (hu << 7) + w];
    float dn = g_sp[0][base + (hd << 7) + w] + g_sp[1][base + (hd << 7) + w];
    float lf = g_sp[0][base + (h << 7) + wl] + g_sp[1][base + (h << 7) + wl];
    float rt = g_sp[0][base + (h << 7) + wr] + g_sp[1][base + (h << 7) + wr];
    g_d[idx] = THETA * (up + dn + lf + rt - 4.f * c);
}

// zero the pad rows hp=0 and hp=129
__global__ void k_zero() {
    int i = blockIdx.x * blockDim.x + threadIdx.x;   // 262144 float4s total
    int b = i >> 13, rem = i & 8191;
    int pr = rem >> 12, j = rem & 4095;
    size_t off = ((size_t)(b * 130 + (pr ? 129 : 0))) * 65536 + (size_t)j * 16;
    *(float4*)(g_xTp + off) = make_float4(0.f, 0.f, 0.f, 0.f);
}

// weights: fp16 hi + SW128-bake; block index ((cc*3+kw)*3+kh)
__global__ void k_prep_w(const float* __restrict__ W) {
    int cc = blockIdx.x, kh = blockIdx.y, kw = blockIdx.z;
    size_t base = (size_t)((cc * 3 + kw) * 3 + kh) * 16384;
    for (int i = threadIdx.x; i < 8192; i += 256) {
        int co = i >> 6, ci = i & 63;
        float v = W[((size_t)co * 128 + cc * 64 + ci) * 9 + kh * 3 + kw];
        uint32_t sw = swz((uint32_t)co * 128 + ci * 2);
        *(unsigned short*)(g_Wp + base + sw) = __half_as_ushort(__float2half(v));
    }
}

// x: transpose [ci][w] -> [w][ci], fp16 hi/lo split, bake swizzle, + chansum
__global__ void k_prep_x(const float* __restrict__ x) {
    extern __shared__ char ps[];
    float* xin = (float*)ps;                                  // [64][129]
    unsigned short* oh = (unsigned short*)(ps + 33024);       // 16KB
    unsigned short* ol = (unsigned short*)(ps + 49408);       // 16KB
    int cc = blockIdx.x, h = blockIdx.y, b = blockIdx.z;
    const float* src = x + (size_t)b * IMG + ((size_t)cc * 64) * 16384 + (size_t)h * 128;
    for (int i = threadIdx.x; i < 8192; i += 256) {
        int ci = i >> 7, w = i & 127;
        xin[ci * 129 + w] = src[(size_t)ci * 16384 + w];
    }
    __syncthreads();
    if (threadIdx.x < 128) {
        int w = threadIdx.x;
        float s = 0.f;
#pragma unroll 16
        for (int ci = 0; ci < 64; ++ci) s += xin[ci * 129 + w];
        g_sp[cc][((size_t)b << 14) + ((size_t)h << 7) + w] = s;
    }
    for (int i = threadIdx.x; i < 8192; i += 256) {
        int w = i >> 6, ci = i & 63;
        float v = xin[ci * 129 + w];
        __half hh = __float2half(v);
        __half ll = __float2half(v - __half2float(hh));
        uint32_t sw = swz((uint32_t)w * 128 + ci * 2);
        oh[sw >> 1] = __half_as_ushort(hh);
        ol[sw >> 1] = __half_as_ushort(ll);
    }
    __syncthreads();
    unsigned char* dst = g_xTp + ((size_t)((b * 130 + h + 1) * 2 + cc) * 2) * 16384;
    float4* d0 = (float4*)dst;
    const float4* s0 = (const float4*)oh;
    const float4* s1 = (const float4*)ol;
    for (int i = threadIdx.x; i < 1024; i += 256) { d0[i] = s0[i]; d0[1024 + i] = s1[i]; }
}

// ---------------- main mma.sync kernel ---------------------------------------
// SMEM: [8],[16],[24] mbarriers; [256..384) zero row;
//       X: 1024 + 6*16384 = 98304 ([kh][sx] blocks)   (reused as outs[128][132])
//       W: 99328 + 2*16384 (double-buffered hi chunk)  -> total 132096
#define X_OFF 1024u
#define W_OFF 99328u
#define SMEM_TOTAL 132096

__global__ void __launch_bounds__(512, 1) k_main(const float* __restrict__ bias,
                                                 float* __restrict__ out) {
    extern __shared__ __align__(1024) char smem[];
    uint32_t sb = smem_u32(smem);
    const int tid = threadIdx.x, wid = tid >> 5, lane = tid & 31;
    const int co_g = wid >> 1, n_g = wid & 1;   // warp = 16 co x 64 w
    const int h = blockIdx.x, b = blockIdx.y;
    const unsigned char* xp = g_xTp + (size_t)b * 130 * 65536;
    const uint32_t zaddr = sb + 256;

    if (tid == 0) { MBAR_INIT(sb + 8, 1); MBAR_INIT(sb + 16, 1); MBAR_INIT(sb + 24, 1); }
    if (tid < 32) ((float*)(smem + 256))[tid] = 0.f;

    // prologue: X for cc=0, W chunks 0 and 1
    if (tid == 0) {
        MBAR_EXPECT_TX(sb + 8, 98304u);
#pragma unroll
        for (int kh = 0; kh < 3; ++kh)
#pragma unroll
            for (int sx = 0; sx < 2; ++sx)
                bulk_g2s(sb + X_OFF + (uint32_t)(kh * 2 + sx) * 16384u,
                         xp + (size_t)((h + kh) * 4 + sx) * 16384, 16384u, sb + 8);
        MBAR_EXPECT_TX(sb + 16, 16384u);
        bulk_g2s(sb + W_OFF, g_Wp, 16384u, sb + 16);
        MBAR_EXPECT_TX(sb + 24, 16384u);
        bulk_g2s(sb + W_OFF + 16384u, g_Wp + 16384, 16384u, sb + 24);
    }
    __syncthreads();   // zero-row + mbar init visible

    // ldmatrix per-thread coordinates (verified mapping from R4)
    const int a_row = co_g * 16 + ((lane & 7) | (((lane >> 3) & 1) << 3));
    const uint32_t a_kb = (uint32_t)((lane >> 4) << 4);
    const int b_n  = (lane & 7) + ((lane >> 4) << 3) + n_g * 64;
    const uint32_t b_kb = (uint32_t)(((lane >> 3) & 1) << 4);
    const uint32_t a_xor = (uint32_t)((a_row & 7) << 4);

    float C[8][4];
#pragma unroll
    for (int nt = 0; nt < 8; ++nt)
#pragma unroll
        for (int i = 0; i < 4; ++i) C[nt][i] = 0.f;

    for (int q = 0; q < 18; ++q) {
        const int r9 = q % 9, kw = r9 / 3, kh = r9 % 3;

        if (q == 9 && tid == 0) {   // reload X for cc=1 (cc=0 fully consumed)
            MBAR_EXPECT_TX(sb + 8, 98304u);
#pragma unroll
            for (int k2 = 0; k2 < 3; ++k2)
#pragma unroll
                for (int sx = 0; sx < 2; ++sx)
                    bulk_g2s(sb + X_OFF + (uint32_t)(k2 * 2 + sx) * 16384u,
                             xp + (size_t)((h + k2) * 4 + 2 + sx) * 16384, 16384u, sb + 8);
        }
        if (q == 0) mbar_wait(sb + 8, 0);
        if (q == 9) mbar_wait(sb + 8, 1);
        mbar_wait(sb + 16u + (uint32_t)((q & 1) << 3), (uint32_t)(q >> 1) & 1u);

        const uint32_t a_base = sb + W_OFF + (uint32_t)((q & 1) << 14)
                              + (uint32_t)a_row * 128u;
        const uint32_t xb = sb + X_OFF + (uint32_t)(kh * 2) * 16384u;

        // per-stage B row bases (kw folded as +-1 row shift; OOB -> zero row)
        uint32_t rh[4], rl[4], rx[4];
#pragma unroll
        for (int ntp = 0; ntp < 4; ++ntp) {
            int r = b_n + ntp * 16 + kw - 1;
            if ((unsigned)r > 127u) {
                rh[ntp] = zaddr; rl[ntp] = zaddr; rx[ntp] = 0u;
            } else {
                rh[ntp] = xb + (uint32_t)r * 128u;
                rl[ntp] = rh[ntp] + 16384u;
                rx[ntp] = (uint32_t)((r & 7) << 4);
            }
        }

#pragma unroll
        for (int ks = 0; ks < 4; ++ks) {
            const uint32_t koA = (uint32_t)(ks * 32) + a_kb;
            const uint32_t koB = (uint32_t)(ks * 32) + b_kb;
            uint32_t ah[4], bh[16], bl[16];
            ldsm4(ah, a_base + (koA ^ a_xor));
#pragma unroll
            for (int ntp = 0; ntp < 4; ++ntp) {
                uint32_t o = koB ^ rx[ntp];
                ldsm4(&bh[ntp * 4], rh[ntp] + o);
                ldsm4(&bl[ntp * 4], rl[ntp] + o);
            }
#pragma unroll
            for (int nt = 0; nt < 8; ++nt)
                mma16816(C[nt], ah, &bh[((nt >> 1) << 2) + ((nt & 1) << 1)]);
#pragma unroll
            for (int nt = 0; nt < 8; ++nt)
                mma16816(C[nt], ah, &bl[((nt >> 1) << 2) + ((nt & 1) << 1)]);
        }

        __syncthreads();   // buffer q fully consumed before refill
        if (tid == 0 && q + 2 < 18) {
            uint32_t mb = sb + 16u + (uint32_t)((q & 1) << 3);
            MBAR_EXPECT_TX(mb, 16384u);
            bulk_g2s(sb + W_OFF + (uint32_t)((q & 1) << 14),
                     g_Wp + (size_t)(q + 2) * 16384, 16384u, mb);
        }
    }

    // ---- epilogue: stage C into SMEM (reuse X region), then coalesced out ----
    float* outs = (float*)(smem + X_OFF);   // [128 co][132]
    {
        const int row0 = co_g * 16 + (lane >> 2);
        const int col0 = n_g * 64 + 2 * (lane & 3);
#pragma unroll
        for (int nt = 0; nt < 8; ++nt) {
            int c = col0 + nt * 8;
            *(float2*)&outs[row0 * 132 + c]       = make_float2(C[nt][0], C[nt][1]);
            *(float2*)&outs[(row0 + 8) * 132 + c] = make_float2(C[nt][2], C[nt][3]);
        }
    }
    __syncthreads();
    const float* gd = g_d + ((size_t)b << 14) + ((size_t)h << 7);
    for (int i = tid; i < 4096; i += 512) {
        int co = i >> 5, w4 = (i & 31) << 2;
        float4 v = *(const float4*)&outs[co * 132 + w4];
        float4 g = *(const float4*)&gd[w4];
        float bv = __ldg(&bias[co]);
        v.x += bv - g.x; v.y += bv - g.y; v.z += bv - g.z; v.w += bv - g.w;
        *(float4*)&out[(size_t)b * IMG + ((size_t)co << 14) + ((size_t)h << 7) + w4] = v;
    }
}

// ---------------------------------------------------------------------------
extern "C" void kernel_launch(void* const* d_in, const int* in_sizes, int n_in,
                              void* d_out, int out_size) {
    const float* x  = (const float*)d_in[0];
    const float* Wt = (const float*)d_in[1];
    const float* bb = (const float*)d_in[2];
    float* out = (float*)d_out;
    (void)in_sizes; (void)n_in; (void)out_size;

    cudaFuncSetAttribute(k_prep_x, cudaFuncAttributeMaxDynamicSharedMemorySize, 65792);
    cudaFuncSetAttribute(k_main,   cudaFuncAttributeMaxDynamicSharedMemorySize, SMEM_TOTAL);

    k_prep_w<<<dim3(2, 3, 3), 256>>>(Wt);
    k_zero<<<1024, 256>>>();
    k_prep_x<<<dim3(2, 128, 32), 256, 65792>>>(x);
    k_stencil<<<NB * HWSZ / 256, 256>>>();
    k_main<<<dim3(128, 32), 512, SMEM_TOTAL>>>(bb, out);
}

// round 7
// speedup vs baseline: 5.7122x; 1.4589x over previous
#include <cuda_runtime.h>
#include <cuda_fp16.h>
#include <cstdint>

#define THETA 0.7f
#define NB   32
#define NC   128
#define NH   128
#define NW   128
#define HWSZ (NH * NW)
#define IMG  (NC * HWSZ)

// ---------------- scratch (static device memory; no allocation) -------------
// xTp: [b][hp=h+1 (0..129)][cc(2)] 16KB blocks, each [128 w][64 ci] fp16 (hi),
// SW128 swizzle baked into the byte layout.
static __device__ __align__(1024) unsigned char g_xTp[(size_t)32 * 130 * 2 * 16384];
// Wp: 18 blocks [cc(2)][kw(3)][kh(3)], each 16KB [128 co][64 ci] fp16.
static __device__ __align__(1024) unsigned char g_Wp[18 * 16384];
static __device__ float g_sp[2][NB * HWSZ];   // partial channel sums
static __device__ float g_d[NB * HWSZ];       // THETA * stencil

// ---------------- PTX helpers ----------------------------------------------
__device__ __forceinline__ uint32_t smem_u32(const void* p) {
    uint32_t a;
    asm("{ .reg .u64 t; cvta.to.shared.u64 t, %1; cvt.u32.u64 %0, t; }" : "=r"(a) : "l"(p));
    return a;
}
#define MBAR_INIT(a, n) asm volatile("mbarrier.init.shared.b64 [%0], %1;" :: "r"(a), "r"(n) : "memory")
#define MBAR_EXPECT_TX(a, b) asm volatile("mbarrier.arrive.expect_tx.shared.b64 _, [%0], %1;" :: "r"(a), "r"(b) : "memory")
__device__ __forceinline__ void mbar_wait(uint32_t mbar, uint32_t parity) {
    asm volatile(
        "{\n\t.reg .pred P;\n\t"
        "W_%=:\n\t"
        "mbarrier.try_wait.parity.acquire.cta.shared::cta.b64 P, [%0], %1, 0x989680;\n\t"
        "@!P bra W_%=;\n\t}" :: "r"(mbar), "r"(parity) : "memory");
}
__device__ __forceinline__ void bulk_g2s(uint32_t dst, const void* src, uint32_t bytes, uint32_t mbar) {
    asm volatile(
        "cp.async.bulk.shared::cta.global.mbarrier::complete_tx::bytes [%0], [%1], %2, [%3];"
        :: "r"(dst), "l"(src), "r"(bytes), "r"(mbar) : "memory");
}
__device__ __forceinline__ void ldsm4(uint32_t* r, uint32_t addr) {
    asm volatile("ldmatrix.sync.aligned.m8n8.x4.shared.b16 {%0,%1,%2,%3}, [%4];"
                 : "=r"(r[0]), "=r"(r[1]), "=r"(r[2]), "=r"(r[3]) : "r"(addr));
}
__device__ __forceinline__ void mma16816(float* c, const uint32_t* a, const uint32_t* b) {
    asm volatile(
        "mma.sync.aligned.m16n8k16.row.col.f32.f16.f16.f32 "
        "{%0,%1,%2,%3}, {%4,%5,%6,%7}, {%8,%9}, {%0,%1,%2,%3};"
        : "+f"(c[0]), "+f"(c[1]), "+f"(c[2]), "+f"(c[3])
        : "r"(a[0]), "r"(a[1]), "r"(a[2]), "r"(a[3]), "r"(b[0]), "r"(b[1]));
}
__device__ __forceinline__ uint32_t swz(uint32_t x) { return x ^ ((x >> 3) & 0x70); }

// ---------------- pre-pass kernels ------------------------------------------
__global__ void k_stencil() {
    int idx = blockIdx.x * blockDim.x + threadIdx.x;
    int b = idx >> 14, hw = idx & (HWSZ - 1);
    int h = hw >> 7, w = hw & 127;
    int base = b << 14;
    int hu = (h > 0   ? h - 1 : 0  ), hd = (h < 127 ? h + 1 : 127);
    int wl = (w > 0   ? w - 1 : 0  ), wr = (w < 127 ? w + 1 : 127);
    float c  = g_sp[0][base + hw]            + g_sp[1][base + hw];
    float up = g_sp[0][base + (hu << 7) + w] + g_sp[1][base + (hu << 7) + w];
    float dn = g_sp[0][base + (hd << 7) + w] + g_sp[1][base + (hd << 7) + w];
    float lf = g_sp[0][base + (h << 7) + wl] + g_sp[1][base + (h << 7) + wl];
    float rt = g_sp[0][base + (h << 7) + wr] + g_sp[1][base + (h << 7) + wr];
    g_d[idx] = THETA * (up + dn + lf + rt - 4.f * c);
}

// zero the pad rows hp=0 and hp=129 (2 blocks = 32KB per pad row per b)
__global__ void k_zero() {
    int i = blockIdx.x * blockDim.x + threadIdx.x;   // 131072 float4s total
    int b = i >> 12, rem = i & 4095;
    int pr = rem >> 11, j = rem & 2047;
    size_t off = ((size_t)(b * 130 + (pr ? 129 : 0))) * 32768 + (size_t)j * 16;
    *(float4*)(g_xTp + off) = make_float4(0.f, 0.f, 0.f, 0.f);
}

// weights: fp16 + SW128-bake; block index ((cc*3+kw)*3+kh)
__global__ void k_prep_w(const float* __restrict__ W) {
    int cc = blockIdx.x, kh = blockIdx.y, kw = blockIdx.z;
    size_t base = (size_t)((cc * 3 + kw) * 3 + kh) * 16384;
    for (int i = threadIdx.x; i < 8192; i += 256) {
        int co = i >> 6, ci = i & 63;
        float v = W[((size_t)co * 128 + cc * 64 + ci) * 9 + kh * 3 + kw];
        uint32_t sw = swz((uint32_t)co * 128 + ci * 2);
        *(unsigned short*)(g_Wp + base + sw) = __half_as_ushort(__float2half(v));
    }
}

// x: transpose [ci][w] -> [w][ci], fp16, bake swizzle, + partial chansum
__global__ void k_prep_x(const float* __restrict__ x) {
    extern __shared__ char ps[];
    float* xin = (float*)ps;                                  // [64][129]
    unsigned short* oh = (unsigned short*)(ps + 33024);       // 16KB
    int cc = blockIdx.x, h = blockIdx.y, b = blockIdx.z;
    const float* src = x + (size_t)b * IMG + ((size_t)cc * 64) * 16384 + (size_t)h * 128;
    for (int i = threadIdx.x; i < 8192; i += 256) {
        int ci = i >> 7, w = i & 127;
        xin[ci * 129 + w] = src[(size_t)ci * 16384 + w];
    }
    __syncthreads();
    if (threadIdx.x < 128) {
        int w = threadIdx.x;
        float s = 0.f;
#pragma unroll 16
        for (int ci = 0; ci < 64; ++ci) s += xin[ci * 129 + w];
        g_sp[cc][((size_t)b << 14) + ((size_t)h << 7) + w] = s;
    }
    for (int i = threadIdx.x; i < 8192; i += 256) {
        int w = i >> 6, ci = i & 63;
        uint32_t sw = swz((uint32_t)w * 128 + ci * 2);
        oh[sw >> 1] = __half_as_ushort(__float2half(xin[ci * 129 + w]));
    }
    __syncthreads();
    unsigned char* dst = g_xTp + ((size_t)((b * 130 + h + 1) * 2 + cc)) * 16384;
    float4* d0 = (float4*)dst;
    const float4* s0 = (const float4*)oh;
    for (int i = threadIdx.x; i < 1024; i += 256) d0[i] = s0[i];
}

// ---------------- main mma.sync kernel ---------------------------------------
// SMEM: [8] xbar, [16],[24] wbar0/1; [256..384) zero row;
//       X: 1024 + 6*16384 = 98304 ([cc][kh] blocks, hi only, resident)
//       W: 99328 + 2*16384 (double-buffered chunk)  -> total 132096
// X region reused as outs[128][132] in the epilogue.
#define X_OFF 1024u
#define W_OFF 99328u
#define SMEM_TOTAL 132096

__global__ void __launch_bounds__(512, 1) k_main(const float* __restrict__ bias,
                                                 float* __restrict__ out) {
    extern __shared__ __align__(1024) char smem[];
    uint32_t sb = smem_u32(smem);
    const int tid = threadIdx.x, wid = tid >> 5, lane = tid & 31;
    const int co_g = wid >> 1, n_g = wid & 1;   // warp = 16 co x 64 w
    const int h = blockIdx.x, b = blockIdx.y;
    const unsigned char* xp = g_xTp + (size_t)b * 130 * 32768;
    const uint32_t zaddr = sb + 256;

    if (tid == 0) { MBAR_INIT(sb + 8, 1); MBAR_INIT(sb + 16, 1); MBAR_INIT(sb + 24, 1); }
    if (tid < 32) ((float*)(smem + 256))[tid] = 0.f;

    // prologue: all 6 X blocks (96KB), W chunks 0 and 1
    if (tid == 0) {
        MBAR_EXPECT_TX(sb + 8, 98304u);
#pragma unroll
        for (int kh = 0; kh < 3; ++kh)
#pragma unroll
            for (int cc = 0; cc < 2; ++cc)
                bulk_g2s(sb + X_OFF + (uint32_t)(cc * 3 + kh) * 16384u,
                         xp + (size_t)((h + kh) * 2 + cc) * 16384, 16384u, sb + 8);
        MBAR_EXPECT_TX(sb + 16, 16384u);
        bulk_g2s(sb + W_OFF, g_Wp, 16384u, sb + 16);
        MBAR_EXPECT_TX(sb + 24, 16384u);
        bulk_g2s(sb + W_OFF + 16384u, g_Wp + 16384, 16384u, sb + 24);
    }
    __syncthreads();   // zero-row + mbar init visible

    // ldmatrix per-thread coordinates (verified mapping from R4/R5)
    const int a_row = co_g * 16 + ((lane & 7) | (((lane >> 3) & 1) << 3));
    const uint32_t a_kb = (uint32_t)((lane >> 4) << 4);
    const int b_n  = (lane & 7) + ((lane >> 4) << 3) + n_g * 64;
    const uint32_t b_kb = (uint32_t)(((lane >> 3) & 1) << 4);
    const uint32_t a_xor = (uint32_t)((a_row & 7) << 4);

    float C[8][4];
#pragma unroll
    for (int nt = 0; nt < 8; ++nt)
#pragma unroll
        for (int i = 0; i < 4; ++i) C[nt][i] = 0.f;

    for (int q = 0; q < 18; ++q) {
        const int cc = q / 9, r9 = q % 9, kw = r9 / 3, kh = r9 % 3;

        if (q == 0) mbar_wait(sb + 8, 0);
        mbar_wait(sb + 16u + (uint32_t)((q & 1) << 3), (uint32_t)(q >> 1) & 1u);

        const uint32_t a_base = sb + W_OFF + (uint32_t)((q & 1) << 14)
                              + (uint32_t)a_row * 128u;
        const uint32_t xb = sb + X_OFF + (uint32_t)(cc * 3 + kh) * 16384u;

        // per-stage B row bases (kw folded as +-1 row shift; OOB -> zero row)
        uint32_t rh[4], rx[4];
#pragma unroll
        for (int ntp = 0; ntp < 4; ++ntp) {
            int r = b_n + ntp * 16 + kw - 1;
            if ((unsigned)r > 127u) {
                rh[ntp] = zaddr; rx[ntp] = 0u;
            } else {
                rh[ntp] = xb + (uint32_t)r * 128u;
                rx[ntp] = (uint32_t)((r & 7) << 4);
            }
        }

#pragma unroll
        for (int ks = 0; ks < 4; ++ks) {
            const uint32_t koA = (uint32_t)(ks * 32) + a_kb;
            const uint32_t koB = (uint32_t)(ks * 32) + b_kb;
            uint32_t ah[4], bh[16];
            ldsm4(ah, a_base + (koA ^ a_xor));
#pragma unroll
            for (int ntp = 0; ntp < 4; ++ntp)
                ldsm4(&bh[ntp * 4], rh[ntp] + (koB ^ rx[ntp]));
#pragma unroll
            for (int nt = 0; nt < 8; ++nt)
                mma16816(C[nt], ah, &bh[((nt >> 1) << 2) + ((nt & 1) << 1)]);
        }

        __syncthreads();   // W buffer q fully consumed before refill
        if (tid == 0 && q + 2 < 18) {
            uint32_t mb = sb + 16u + (uint32_t)((q & 1) << 3);
            MBAR_EXPECT_TX(mb, 16384u);
            bulk_g2s(sb + W_OFF + (uint32_t)((q & 1) << 14),
                     g_Wp + (size_t)(q + 2) * 16384, 16384u, mb);
        }
    }

    // ---- epilogue: stage C into SMEM (reuse X region), then coalesced out ----
    float* outs = (float*)(smem + X_OFF);   // [128 co][132]
    {
        const int row0 = co_g * 16 + (lane >> 2);
        const int col0 = n_g * 64 + 2 * (lane & 3);
#pragma unroll
        for (int nt = 0; nt < 8; ++nt) {
            int c = col0 + nt * 8;
            *(float2*)&outs[row0 * 132 + c]       = make_float2(C[nt][0], C[nt][1]);
            *(float2*)&outs[(row0 + 8) * 132 + c] = make_float2(C[nt][2], C[nt][3]);
        }
    }
    __syncthreads();
    const float* gd = g_d + ((size_t)b << 14) + ((size_t)h << 7);
    for (int i = tid; i < 4096; i += 512) {
        int co = i >> 5, w4 = (i & 31) << 2;
        float4 v = *(const float4*)&outs[co * 132 + w4];
        float4 g = *(const float4*)&gd[w4];
        float bv = __ldg(&bias[co]);
        v.x += bv - g.x; v.y += bv - g.y; v.z += bv - g.z; v.w += bv - g.w;
        *(float4*)&out[(size_t)b * IMG + ((size_t)co << 14) + ((size_t)h << 7) + w4] = v;
    }
}

// ---------------------------------------------------------------------------
extern "C" void kernel_launch(void* const* d_in, const int* in_sizes, int n_in,
                              void* d_out, int out_size) {
    const float* x  = (const float*)d_in[0];
    const float* Wt = (const float*)d_in[1];
    const float* bb = (const float*)d_in[2];
    float* out = (float*)d_out;
    (void)in_sizes; (void)n_in; (void)out_size;

    cudaFuncSetAttribute(k_prep_x, cudaFuncAttributeMaxDynamicSharedMemorySize, 49408);
    cudaFuncSetAttribute(k_main,   cudaFuncAttributeMaxDynamicSharedMemorySize, SMEM_TOTAL);

    k_prep_w<<<dim3(2, 3, 3), 256>>>(Wt);
    k_zero<<<512, 256>>>();
    k_prep_x<<<dim3(2, 128, 32), 256, 49408>>>(x);
    k_stencil<<<NB * HWSZ / 256, 256>>>();
    k_main<<<dim3(128, 32), 512, SMEM_TOTAL>>>(bb, out);
}

// round 8
// speedup vs baseline: 7.5600x; 1.3235x over previous
#include <cuda_runtime.h>
#include <cuda_fp16.h>
#include <cstdint>

#define THETA 0.7f
#define NB   32
#define NC   128
#define NH   128
#define NW   128
#define HWSZ (NH * NW)
#define IMG  (NC * HWSZ)

// ---------------- scratch (static device memory; no allocation) -------------
// xTp: [b][hp=h+1 (0..129)][cc(2)] 16KB blocks, each [128 w][64 ci] fp16,
// SW128 swizzle baked into the byte layout.
static __device__ __align__(1024) unsigned char g_xTp[(size_t)32 * 130 * 2 * 16384];
// Wp: 18 blocks ordered [cc(2)][kh(3)][kw(3)], each 16KB [128 co][64 ci] fp16.
static __device__ __align__(1024) unsigned char g_Wp[18 * 16384];
static __device__ float g_sp[2][NB * HWSZ];   // partial channel sums
static __device__ float g_d[NB * HWSZ];       // THETA * stencil

// ---------------- PTX helpers ----------------------------------------------
__device__ __forceinline__ uint32_t smem_u32(const void* p) {
    uint32_t a;
    asm("{ .reg .u64 t; cvta.to.shared.u64 t, %1; cvt.u32.u64 %0, t; }" : "=r"(a) : "l"(p));
    return a;
}
#define MBAR_INIT(a, n) asm volatile("mbarrier.init.shared.b64 [%0], %1;" :: "r"(a), "r"(n) : "memory")
#define MBAR_EXPECT_TX(a, b) asm volatile("mbarrier.arrive.expect_tx.shared.b64 _, [%0], %1;" :: "r"(a), "r"(b) : "memory")
__device__ __forceinline__ void mbar_wait(uint32_t mbar, uint32_t parity) {
    asm volatile(
        "{\n\t.reg .pred P;\n\t"
        "W_%=:\n\t"
        "mbarrier.try_wait.parity.acquire.cta.shared::cta.b64 P, [%0], %1, 0x989680;\n\t"
        "@!P bra W_%=;\n\t}" :: "r"(mbar), "r"(parity) : "memory");
}
__device__ __forceinline__ void bulk_g2s(uint32_t dst, const void* src, uint32_t bytes, uint32_t mbar) {
    asm volatile(
        "cp.async.bulk.shared::cta.global.mbarrier::complete_tx::bytes [%0], [%1], %2, [%3];"
        :: "r"(dst), "l"(src), "r"(bytes), "r"(mbar) : "memory");
}
__device__ __forceinline__ void ldsm4(uint32_t* r, uint32_t addr) {
    asm volatile("ldmatrix.sync.aligned.m8n8.x4.shared.b16 {%0,%1,%2,%3}, [%4];"
                 : "=r"(r[0]), "=r"(r[1]), "=r"(r[2]), "=r"(r[3]) : "r"(addr));
}
__device__ __forceinline__ void mma16816(float* c, const uint32_t* a, const uint32_t* b) {
    asm volatile(
        "mma.sync.aligned.m16n8k16.row.col.f32.f16.f16.f32 "
        "{%0,%1,%2,%3}, {%4,%5,%6,%7}, {%8,%9}, {%0,%1,%2,%3};"
        : "+f"(c[0]), "+f"(c[1]), "+f"(c[2]), "+f"(c[3])
        : "r"(a[0]), "r"(a[1]), "r"(a[2]), "r"(a[3]), "r"(b[0]), "r"(b[1]));
}
__device__ __forceinline__ uint32_t swz(uint32_t x) { return x ^ ((x >> 3) & 0x70); }

// ---------------- pre-pass kernels ------------------------------------------
__global__ void k_stencil() {
    int idx = blockIdx.x * blockDim.x + threadIdx.x;
    int b = idx >> 14, hw = idx & (HWSZ - 1);
    int h = hw >> 7, w = hw & 127;
    int base = b << 14;
    int hu = (h > 0   ? h - 1 : 0  ), hd = (h < 127 ? h + 1 : 127);
    int wl = (w > 0   ? w - 1 : 0  ), wr = (w < 127 ? w + 1 : 127);
    float c  = g_sp[0][base + hw]            + g_sp[1][base + hw];
    float up = g_sp[0][base + (hu << 7) + w] + g_sp[1][base + (hu << 7) + w];
    float dn = g_sp[0][base + (hd << 7) + w] + g_sp[1][base + (hd << 7) + w];
    float lf = g_sp[0][base + (h << 7) + wl] + g_sp[1][base + (h << 7) + wl];
    float rt = g_sp[0][base + (h << 7) + wr] + g_sp[1][base + (h << 7) + wr];
    g_d[idx] = THETA * (up + dn + lf + rt - 4.f * c);
}

// zero the pad rows hp=0 and hp=129 (2 blocks = 32KB per pad row per b)
__global__ void k_zero() {
    int i = blockIdx.x * blockDim.x + threadIdx.x;   // 131072 float4s total
    int b = i >> 12, rem = i & 4095;
    int pr = rem >> 11, j = rem & 2047;
    size_t off = ((size_t)(b * 130 + (pr ? 129 : 0))) * 32768 + (size_t)j * 16;
    *(float4*)(g_xTp + off) = make_float4(0.f, 0.f, 0.f, 0.f);
}

// weights: fp16 + SW128-bake; block index ((cc*3+kh)*3+kw)
__global__ void k_prep_w(const float* __restrict__ W) {
    int cc = blockIdx.x, kh = blockIdx.y, kw = blockIdx.z;
    size_t base = (size_t)((cc * 3 + kh) * 3 + kw) * 16384;
    for (int i = threadIdx.x; i < 8192; i += 256) {
        int co = i >> 6, ci = i & 63;
        float v = W[((size_t)co * 128 + cc * 64 + ci) * 9 + kh * 3 + kw];
        uint32_t sw = swz((uint32_t)co * 128 + ci * 2);
        *(unsigned short*)(g_Wp + base + sw) = __half_as_ushort(__float2half(v));
    }
}

// x: transpose [ci][w] -> [w][ci], fp16, bake swizzle, + partial chansum
__global__ void k_prep_x(const float* __restrict__ x) {
    extern __shared__ char ps[];
    float* xin = (float*)ps;                                  // [64][129]
    unsigned short* oh = (unsigned short*)(ps + 33024);       // 16KB
    int cc = blockIdx.x, h = blockIdx.y, b = blockIdx.z;
    const float* src = x + (size_t)b * IMG + ((size_t)cc * 64) * 16384 + (size_t)h * 128;
    for (int i = threadIdx.x; i < 8192; i += 256) {
        int ci = i >> 7, w = i & 127;
        xin[ci * 129 + w] = src[(size_t)ci * 16384 + w];
    }
    __syncthreads();
    if (threadIdx.x < 128) {
        int w = threadIdx.x;
        float s = 0.f;
#pragma unroll 16
        for (int ci = 0; ci < 64; ++ci) s += xin[ci * 129 + w];
        g_sp[cc][((size_t)b << 14) + ((size_t)h << 7) + w] = s;
    }
    for (int i = threadIdx.x; i < 8192; i += 256) {
        int w = i >> 6, ci = i & 63;
        uint32_t sw = swz((uint32_t)w * 128 + ci * 2);
        oh[sw >> 1] = __half_as_ushort(__float2half(xin[ci * 129 + w]));
    }
    __syncthreads();
    unsigned char* dst = g_xTp + ((size_t)((b * 130 + h + 1) * 2 + cc)) * 16384;
    float4* d0 = (float4*)dst;
    const float4* s0 = (const float4*)oh;
    for (int i = threadIdx.x; i < 1024; i += 256) d0[i] = s0[i];
}

// ---------------- main mma.sync kernel ---------------------------------------
// CTA = 2 output rows (h0, h0+1) x 128 co x 128 w; 512 threads.
// warp: p = wid&1 (row), n_g = (wid>>1)&1 (64w half), co_g = wid>>2 (32co group)
// SMEM: [8] xbar, [16],[24] wbar0/1; [256..384) zero row;
//       X: 1024 + 8*16384 = 131072  ([d(4)][cc(2)] blocks, resident)
//       W: 132096 + 2*49152 (double-buffered 3-kw chunk) -> total 230400
// X region reused as outs[128][132] in the epilogue.
#define X_OFF 1024u
#define W_OFF 132096u
#define SMEM_TOTAL 230400

__global__ void __launch_bounds__(512, 1) k_main(const float* __restrict__ bias,
                                                 float* __restrict__ out) {
    extern __shared__ __align__(1024) char smem[];
    uint32_t sb = smem_u32(smem);
    const int tid = threadIdx.x, wid = tid >> 5, lane = tid & 31;
    const int p    = wid & 1;
    const int n_g  = (wid >> 1) & 1;
    const int co_g = wid >> 2;            // 0..3
    const int h0 = blockIdx.x * 2, b = blockIdx.y;
    const unsigned char* xp = g_xTp + (size_t)b * 130 * 32768;
    const uint32_t zaddr = sb + 256;

    if (tid == 0) { MBAR_INIT(sb + 8, 1); MBAR_INIT(sb + 16, 1); MBAR_INIT(sb + 24, 1); }
    if (tid < 32) ((float*)(smem + 256))[tid] = 0.f;

    // prologue: 8 X blocks (rows h0-1..h0+2 x 2 cc), W stages 0 and 1 (48KB each)
    if (tid == 0) {
        MBAR_EXPECT_TX(sb + 8, 131072u);
#pragma unroll
        for (int d = 0; d < 4; ++d)
#pragma unroll
            for (int cc = 0; cc < 2; ++cc)
                bulk_g2s(sb + X_OFF + (uint32_t)(d * 2 + cc) * 16384u,
                         xp + (size_t)((h0 + d) * 2 + cc) * 16384, 16384u, sb + 8);
        MBAR_EXPECT_TX(sb + 16, 49152u);
        bulk_g2s(sb + W_OFF, g_Wp, 49152u, sb + 16);
        MBAR_EXPECT_TX(sb + 24, 49152u);
        bulk_g2s(sb + W_OFF + 49152u, g_Wp + 49152, 49152u, sb + 24);
    }
    __syncthreads();   // zero-row + mbar init visible

    // ldmatrix per-thread coordinates (verified mapping)
    const int a_row = co_g * 32 + ((lane & 7) | (((lane >> 3) & 1) << 3));
    const uint32_t a_kb = (uint32_t)((lane >> 4) << 4);
    const int b_n  = (lane & 7) + ((lane >> 4) << 3) + n_g * 64;
    const uint32_t b_kb = (uint32_t)(((lane >> 3) & 1) << 4);
    const uint32_t a_xor = (uint32_t)((a_row & 7) << 4);

    float C[16][4];   // [s16(2) x nt(8)][4]
#pragma unroll
    for (int nt = 0; nt < 16; ++nt)
#pragma unroll
        for (int i = 0; i < 4; ++i) C[nt][i] = 0.f;

    for (int s = 0; s < 6; ++s) {
        const int cc = s / 3, kh = s % 3;

        if (s == 0) mbar_wait(sb + 8, 0);
        mbar_wait(sb + 16u + (uint32_t)((s & 1) << 3), (uint32_t)(s >> 1) & 1u);

        const uint32_t wbuf = sb + W_OFF + (uint32_t)((s & 1) ? 49152u : 0u);
        const uint32_t xb = sb + X_OFF + (uint32_t)((p + kh) * 2 + cc) * 16384u;

#pragma unroll
        for (int kw = 0; kw < 3; ++kw) {
            const uint32_t wkw = wbuf + (uint32_t)kw * 16384u
                               + (uint32_t)a_row * 128u;
            // B row bases (kw folded as +-1 row shift; OOB -> zero row)
            uint32_t rh[4], rx[4];
#pragma unroll
            for (int ntp = 0; ntp < 4; ++ntp) {
                int r = b_n + ntp * 16 + kw - 1;
                if ((unsigned)r > 127u) { rh[ntp] = zaddr; rx[ntp] = 0u; }
                else { rh[ntp] = xb + (uint32_t)r * 128u; rx[ntp] = (uint32_t)((r & 7) << 4); }
            }
#pragma unroll
            for (int ks = 0; ks < 4; ++ks) {
                const uint32_t koA = (uint32_t)(ks * 32) + a_kb;
                const uint32_t koB = (uint32_t)(ks * 32) + b_kb;
                uint32_t ah0[4], ah1[4], bh[16];
                ldsm4(ah0, wkw + (koA ^ a_xor));
                ldsm4(ah1, wkw + 2048u + (koA ^ a_xor));   // +16 rows * 128B
#pragma unroll
                for (int ntp = 0; ntp < 4; ++ntp)
                    ldsm4(&bh[ntp * 4], rh[ntp] + (koB ^ rx[ntp]));
#pragma unroll
                for (int nt = 0; nt < 8; ++nt)
                    mma16816(C[nt], ah0, &bh[((nt >> 1) << 2) + ((nt & 1) << 1)]);
#pragma unroll
                for (int nt = 0; nt < 8; ++nt)
                    mma16816(C[8 + nt], ah1, &bh[((nt >> 1) << 2) + ((nt & 1) << 1)]);
            }
        }

        __syncthreads();   // W buffer s fully consumed before refill
        if (tid == 0 && s + 2 < 6) {
            uint32_t mb = sb + 16u + (uint32_t)((s & 1) << 3);
            MBAR_EXPECT_TX(mb, 49152u);
            bulk_g2s(sb + W_OFF + (uint32_t)((s & 1) ? 49152u : 0u),
                     g_Wp + (size_t)(s + 2) * 49152, 49152u, mb);
        }
    }

    // ---- epilogue: per row, stage C into SMEM (reuse X region), write out ----
    float* outs = (float*)(smem + X_OFF);   // [128 co][132]
    const int row0 = co_g * 32 + (lane >> 2);
    const int col0 = n_g * 64 + 2 * (lane & 3);
#pragma unroll
    for (int pp = 0; pp < 2; ++pp) {
        if (p == pp) {
#pragma unroll
            for (int s16 = 0; s16 < 2; ++s16)
#pragma unroll
                for (int nt = 0; nt < 8; ++nt) {
                    int rr = row0 + s16 * 16;
                    int c = col0 + nt * 8;
                    float* Cp = C[s16 * 8 + nt];
                    *(float2*)&outs[rr * 132 + c]       = make_float2(Cp[0], Cp[1]);
                    *(float2*)&outs[(rr + 8) * 132 + c] = make_float2(Cp[2], Cp[3]);
                }
        }
        __syncthreads();
        const float* gd = g_d + ((size_t)b << 14) + ((size_t)(h0 + pp) << 7);
        for (int i = tid; i < 4096; i += 512) {
            int co = i >> 5, w4 = (i & 31) << 2;
            float4 v = *(const float4*)&outs[co * 132 + w4];
            float4 g = *(const float4*)&gd[w4];
            float bv = __ldg(&bias[co]);
            v.x += bv - g.x; v.y += bv - g.y; v.z += bv - g.z; v.w += bv - g.w;
            *(float4*)&out[(size_t)b * IMG + ((size_t)co << 14)
                           + ((size_t)(h0 + pp) << 7) + w4] = v;
        }
        __syncthreads();
    }
}

// ---------------------------------------------------------------------------
extern "C" void kernel_launch(void* const* d_in, const int* in_sizes, int n_in,
                              void* d_out, int out_size) {
    const float* x  = (const float*)d_in[0];
    const float* Wt = (const float*)d_in[1];
    const float* bb = (const float*)d_in[2];
    float* out = (float*)d_out;
    (void)in_sizes; (void)n_in; (void)out_size;

    cudaFuncSetAttribute(k_prep_x, cudaFuncAttributeMaxDynamicSharedMemorySize, 49408);
    cudaFuncSetAttribute(k_main,   cudaFuncAttributeMaxDynamicSharedMemorySize, SMEM_TOTAL);

    k_prep_w<<<dim3(2, 3, 3), 256>>>(Wt);
    k_zero<<<512, 256>>>();
    k_prep_x<<<dim3(2, 128, 32), 256, 49408>>>(x);
    k_stencil<<<NB * HWSZ / 256, 256>>>();
    k_main<<<dim3(64, 32), 512, SMEM_TOTAL>>>(bb, out);
}